// round 1
// baseline (speedup 1.0000x reference)
#include <cuda_runtime.h>
#include <cuda_bf16.h>

// Problem constants (fixed shapes from reference):
//   x:    (4, 64, 512, 512) fp32
//   iperm:(4, 4) int32
//   out:  (4, 64, 256, 256) fp32
//
// out[b, n*4+k, h, w] = sum_g x[b, g*16+n, 2h + pos/2, 2w + pos%2], pos = iperm[g*4+k]

__device__ __forceinline__ float sel4(float v0, float v1, float v2, float v3, int pos) {
    float a = (pos & 1) ? v1 : v0;   // pos in {0,1}
    float b = (pos & 1) ? v3 : v2;   // pos in {2,3}
    return (pos & 2) ? b : a;
}

__global__ void __launch_bounds__(256, 8)
muxout_transpose_kernel(const float* __restrict__ x,
                        const int*   __restrict__ iperm,
                        float*       __restrict__ out) {
    __shared__ int sp[16];
    if (threadIdx.x < 16) sp[threadIdx.x] = iperm[threadIdx.x];
    __syncthreads();

    // Total threads: B(4) * Ng(16) * H(256) * W/2(128) = 2,097,152
    const unsigned t  = blockIdx.x * 256u + threadIdx.x;
    const int w2 = t & 127;          // 0..127  (covers output w = 2*w2, 2*w2+1)
    const int h  = (t >> 7) & 255;   // 0..255
    const int n  = (t >> 15) & 15;   // 0..15
    const int b  = t >> 19;          // 0..3

    // Per-g values: v[g][pos] for output w = 2*w2 (lo) and 2*w2+1 (hi)
    float lo[4][4];
    float hi[4][4];

    #pragma unroll
    for (int g = 0; g < 4; g++) {
        const size_t chan = (size_t)(b * 64 + g * 16 + n);
        const float4* row0 = reinterpret_cast<const float4*>(
            x + (chan * 512 + (size_t)(2 * h)) * 512) + w2;
        const float4* row1 = row0 + 128;  // next input row (+512 floats)
        const float4 r0 = __ldg(row0);
        const float4 r1 = __ldg(row1);
        // pos = sh*2 + sw
        lo[g][0] = r0.x; lo[g][1] = r0.y; lo[g][2] = r1.x; lo[g][3] = r1.y;
        hi[g][0] = r0.z; hi[g][1] = r0.w; hi[g][2] = r1.z; hi[g][3] = r1.w;
    }

    const size_t out_base = (((size_t)(b * 64 + n * 4)) * 256 + h) * 256 + 2 * w2;

    #pragma unroll
    for (int k = 0; k < 4; k++) {
        float acc_lo = 0.0f, acc_hi = 0.0f;
        #pragma unroll
        for (int g = 0; g < 4; g++) {
            const int pos = sp[g * 4 + k];
            acc_lo += sel4(lo[g][0], lo[g][1], lo[g][2], lo[g][3], pos);
            acc_hi += sel4(hi[g][0], hi[g][1], hi[g][2], hi[g][3], pos);
        }
        float2 o; o.x = acc_lo; o.y = acc_hi;
        *reinterpret_cast<float2*>(out + out_base + (size_t)k * (256 * 256)) = o;
    }
}

extern "C" void kernel_launch(void* const* d_in, const int* in_sizes, int n_in,
                              void* d_out, int out_size) {
    const float* x     = (const float*)d_in[0];
    const int*   iperm = (const int*)d_in[1];
    float*       out   = (float*)d_out;

    // 2,097,152 threads / 256 = 8192 blocks
    muxout_transpose_kernel<<<8192, 256>>>(x, iperm, out);
}